// round 12
// baseline (speedup 1.0000x reference)
#include <cuda_runtime.h>
#include <cstdint>

#define NUM_STEPS 180
#define Bb 2
#define Hh 512
#define Ww 512
#define HW (Hh*Ww)
#define Dd 128
#define Vv (Dd*Dd*Dd)

__device__ float4 g_tpl[Bb*Vv];                 // 67 MB repacked template
__device__ uint4  g_keys[(NUM_STEPS+1)*3];      // expanded per-step key schedule
__device__ unsigned int g_len_min_bits, g_len_max_bits;
__device__ unsigned int g_one;                  // runtime 1: adds become IMAD (fma pipe)

__device__ __forceinline__ uint32_t rotl32(uint32_t x, int r){ return __funnelshift_l(x, x, r); }

// plain threefry for setup
__device__ __forceinline__ uint2 tf2x32(uint32_t k0, uint32_t k1, uint32_t x0, uint32_t x1){
  uint32_t k2 = k0 ^ k1 ^ 0x1BD11BDAu;
  x0 += k0; x1 += k1;
#define TFR(r) { x0 += x1; x1 = rotl32(x1, (r)); x1 ^= x0; }
  TFR(13) TFR(15) TFR(26) TFR(6)
  x0 += k1; x1 += k2 + 1u;
  TFR(17) TFR(29) TFR(16) TFR(24)
  x0 += k2; x1 += k0 + 2u;
  TFR(13) TFR(15) TFR(26) TFR(6)
  x0 += k0; x1 += k1 + 3u;
  TFR(17) TFR(29) TFR(16) TFR(24)
  x0 += k1; x1 += k2 + 4u;
  TFR(13) TFR(15) TFR(26) TFR(6)
  x0 += k2; x1 += k0 + 5u;
#undef TFR
  return make_uint2(x0, x1);
}

// hot-loop threefry: expanded keys from smem; adds written x*one+y so ptxas
// emits IMAD (fma pipe). Pure C, no asm.
__device__ __forceinline__ uint32_t tf_bits(const uint4* ks, uint32_t p, uint32_t one){
  uint4 A = ks[0], B = ks[1], C = ks[2];
  uint32_t x0 = A.x;                       // 0 + k0
  uint32_t x1 = p*one + A.y;               // p + k1
#define TFR(r) { x0 = x0*one + x1; x1 = rotl32(x1, (r)) ^ x0; }
  TFR(13) TFR(15) TFR(26) TFR(6)
  x0 = x0*one + A.z; x1 = x1*one + A.w;    // +k1, +k2+1
  TFR(17) TFR(29) TFR(16) TFR(24)
  x0 = x0*one + B.x; x1 = x1*one + B.y;    // +k2, +k0+2
  TFR(13) TFR(15) TFR(26) TFR(6)
  x0 = x0*one + B.z; x1 = x1*one + B.w;    // +k0, +k1+3
  TFR(17) TFR(29) TFR(16) TFR(24)
  x0 = x0*one + C.x; x1 = x1*one + C.y;    // +k1, +k2+4
  TFR(13) TFR(15) TFR(26) TFR(6)
  x0 = x0*one + C.z; x1 = x1*one + C.w;    // +k2, +k0+5
#undef TFR
  return x0 ^ x1;                          // partitionable-mode bits
}

__global__ void k_setup(){
  int i = threadIdx.x;
  if (i <= NUM_STEPS){
    uint2 k = tf2x32(0u, 42u, 0u, (uint32_t)i);       // fold_in(key(42), i)
    uint32_t k0 = k.x, k1 = k.y, k2 = k0 ^ k1 ^ 0x1BD11BDAu;
    g_keys[3*i+0] = make_uint4(k0, k1, k1, k2+1u);
    g_keys[3*i+1] = make_uint4(k2, k0+2u, k0, k1+3u);
    g_keys[3*i+2] = make_uint4(k1, k2+4u, k2, k0+5u);
  }
  if (i == 0){ g_len_min_bits = 0x7F800000u; g_len_max_bits = 0u; g_one = 1u; }
}

// (B,4,D,D,D) -> (B, D^3, float4)
__global__ void k_pack(const float* __restrict__ tpl){
  int v = blockIdx.x*256 + threadIdx.x;
  int b = v >> 21;
  int r = v & (Vv-1);
  const float* base = tpl + (size_t)b*4*Vv;
  g_tpl[v] = make_float4(base[r], base[Vv+r], base[2*Vv+r], base[3*Vv+r]);
}

// Launch-slot shim: keeps k_march in the ncu profiled slot. No work.
__global__ void k_dummy(){ }

__global__ __launch_bounds__(128) void k_march(
  const float* __restrict__ rot, const float* __restrict__ campos,
  const float* __restrict__ fo,  const float* __restrict__ pp,
  const float* __restrict__ bg,  float* __restrict__ out)
{
  __shared__ uint4 skeys[(NUM_STEPS+1)*3];
  int lt = threadIdx.y*16 + threadIdx.x;
  for (int i = lt; i < (NUM_STEPS+1)*3; i += 128) skeys[i] = g_keys[i];
  __syncthreads();

  const uint32_t one = g_one;

  int w = blockIdx.x*16 + threadIdx.x;
  int h = blockIdx.y*8  + threadIdx.y;
  int b = blockIdx.z;
  int p = b*HW + h*Ww + w;

  float rx = ((float)w - pp[2*b+0]) / fo[2*b+0];
  float ry = ((float)h - pp[2*b+1]) / fo[2*b+1];
  const float* R = rot + 9*b;
  float dx = R[0]*rx + R[3]*ry + R[6];
  float dy = R[1]*rx + R[4]*ry + R[7];
  float dz = R[2]*rx + R[5]*ry + R[8];
  float nrm = sqrtf(dx*dx + dy*dy + dz*dz);
  dx /= nrm; dy /= nrm; dz /= nrm;
  float cxp = campos[3*b+0], cyp = campos[3*b+1], czp = campos[3*b+2];

  float t1x = (-1.0f-cxp)/dx, t2x = (1.0f-cxp)/dx;
  float t1y = (-1.0f-cyp)/dy, t2y = (1.0f-cyp)/dy;
  float t1z = (-1.0f-czp)/dz, t2z = (1.0f-czp)/dz;
  float tmin = fmaxf(fminf(t1x,t2x), fmaxf(fminf(t1y,t2y), fminf(t1z,t2z)));
  float tmax = fminf(fmaxf(t1x,t2x), fminf(fmaxf(t1y,t2y), fmaxf(t1z,t2z)));
  float t = (tmin < tmax) ? tmin : 0.0f;
  t = fmaxf(t, 0.0f);

  { // t jitter: uniform under fold_in(key,0)
    uint32_t bits = tf_bits(skeys, (uint32_t)p, one);
    float u = __uint_as_float((bits >> 9) | 0x3f800000u) - 1.0f;
    t = t - 0.02f * u;
  }

  float px = cxp + dx*t, py = cyp + dy*t, pz = czp + dz*t;
  float r0_=0.f, r1_=0.f, r2_=0.f, al=0.f, len=0.f;
  const float4* tp = g_tpl + (size_t)b*Vv;
  const float LO = -0.99999994f;
  const float LOm2 = LO - 2.0f;             // -2.99999994f, representable

  for (int i = 0; i < NUM_STEPS; i++){
    uint32_t bits = tf_bits(skeys + 3*(i+1), (uint32_t)p, one);
    float mant = __uint_as_float((bits >> 9) | 0x3f800000u);   // [1,2)
    float uu = fmaxf(LO, fmaf(mant, 2.0f, LOm2));
    // y = 0.01*sqrt(2)*erfinv(uu) in [-0.076, 0.076]
    float y = 0.014142136f * erfinvf(uu);
    // stepv = 0.02*exp(y) via cubic Taylor (rel err <= 1.4e-6 on this range)
    float stepv = fmaf(y, fmaf(y, fmaf(y, 0.0033333333f, 0.01f), 0.02f), 0.02f);

    float m = fmaxf(fmaxf(fabsf(px), fabsf(py)), fabsf(pz));
    float contrib = 0.0f;
    if (m < 1.0f && al < 1.0f){
      // inside ⇒ g in [0,127]; reference clip() is a no-op here.
      float gx = fmaf(px, 63.5f, 63.5f);
      float gy = fmaf(py, 63.5f, 63.5f);
      float gz = fmaf(pz, 63.5f, 63.5f);
      float x0f = floorf(gx), y0f = floorf(gy), z0f = floorf(gz);
      int x0 = (int)x0f; int x1 = min(x0+1,127); float wx = gx - x0f;
      int y0 = (int)y0f; int y1 = min(y0+1,127); float wy = gy - y0f;
      int z0 = (int)z0f; int z1 = min(z0+1,127); float wz = gz - z0f;
      int zy00 = (z0*Dd + y0)*Dd, zy01 = (z0*Dd + y1)*Dd;
      int zy10 = (z1*Dd + y0)*Dd, zy11 = (z1*Dd + y1)*Dd;
      float4 v000 = tp[zy00 + x0], v001 = tp[zy00 + x1];
      float4 v010 = tp[zy01 + x0], v011 = tp[zy01 + x1];
      float4 v100 = tp[zy10 + x0], v101 = tp[zy10 + x1];
      float4 v110 = tp[zy11 + x0], v111 = tp[zy11 + x1];
      float iwx = 1.0f - wx, iwy = 1.0f - wy, iwz = 1.0f - wz;

      // weight-form trilinear: 12 muls + 4x(1 mul + 7 fma) = 44 instrs
      float wxy = wx*wy,  ixy = iwx*wy,  xiy = wx*iwy,  ixiy = iwx*iwy;
      float w000 = ixiy*iwz, w001 = xiy*iwz, w010 = ixy*iwz, w011 = wxy*iwz;
      float w100 = ixiy*wz,  w101 = xiy*wz,  w110 = ixy*wz,  w111 = wxy*wz;
#define DOT8(dst, ch) \
      dst = v000.ch*w000 + v001.ch*w001 + v010.ch*w010 + v011.ch*w011 \
          + v100.ch*w100 + v101.ch*w101 + v110.ch*w110 + v111.ch*w111;
      float s0,s1,s2,s3;
      DOT8(s0,x) DOT8(s1,y) DOT8(s2,z) DOT8(s3,w)
#undef DOT8

      contrib = fminf(al + s3*stepv, 1.0f) - al;
      r0_ += s0*contrib; r1_ += s1*contrib; r2_ += s2*contrib;
      al += contrib;
    }
    len += (contrib == 0.0f) ? stepv : 0.0f;
    px += dx*stepv; py += dy*stepv; pz += dz*stepv;
  }

  int pix = h*Ww + w;
  size_t rgbBase = (size_t)b*3*HW + pix;
  float ia = 1.0f - al;
  out[rgbBase       ] = r0_ + ia*fmaxf(bg[(size_t)(3*b+0)*HW + pix], 0.0f);
  out[rgbBase +   HW] = r1_ + ia*fmaxf(bg[(size_t)(3*b+1)*HW + pix], 0.0f);
  out[rgbBase + 2*HW] = r2_ + ia*fmaxf(bg[(size_t)(3*b+2)*HW + pix], 0.0f);
  out[(size_t)Bb*3*HW + b*HW + pix] = al;
  out[(size_t)Bb*4*HW + b*HW + pix] = len;   // raw; normalized by k_norm

  unsigned lb = __float_as_uint(len);
  unsigned mx = __reduce_max_sync(0xffffffffu, lb);
  unsigned mn = __reduce_min_sync(0xffffffffu, lb);
  if ((lt & 31) == 0){ atomicMax(&g_len_max_bits, mx); atomicMin(&g_len_min_bits, mn); }
}

__global__ void k_norm(float* __restrict__ out){
  int i = blockIdx.x*256 + threadIdx.x;
  float denom = __uint_as_float(g_len_max_bits) + __uint_as_float(g_len_min_bits);
  float a = out[(size_t)Bb*3*HW + i];
  float l = out[(size_t)Bb*4*HW + i];
  out[(size_t)Bb*4*HW + i] = (a * l) / denom;
}

extern "C" void kernel_launch(void* const* d_in, const int* in_sizes, int n_in,
                              void* d_out, int out_size) {
  const float* rot    = (const float*)d_in[0];
  const float* campos = (const float*)d_in[1];
  const float* fo     = (const float*)d_in[2];
  const float* pp     = (const float*)d_in[3];
  const float* tpl    = (const float*)d_in[5];
  const float* bg     = (const float*)d_in[6];
  float* out = (float*)d_out;

  k_setup<<<1, 256>>>();
  k_pack<<<(Bb*Vv)/256, 256>>>(tpl);
  k_dummy<<<1, 1>>>();                      // keeps k_march in ncu's profiled slot
  dim3 blk(16,8,1), grd(Ww/16, Hh/8, Bb);
  k_march<<<grd, blk>>>(rot, campos, fo, pp, bg, out);
  k_norm<<<(Bb*HW)/256, 256>>>(out);
}

// round 13
// speedup vs baseline: 1.0855x; 1.0855x over previous
#include <cuda_runtime.h>
#include <cstdint>

#define NUM_STEPS 180
#define Bb 2
#define Hh 512
#define Ww 512
#define HW (Hh*Ww)
#define Dd 128
#define Vv (Dd*Dd*Dd)

__device__ float4 g_tpl[Bb*Vv];                 // 67 MB repacked template
__device__ uint4  g_keys[(NUM_STEPS+1)*3];      // expanded per-step key schedule
__device__ unsigned int g_len_min_bits, g_len_max_bits;
__device__ unsigned int g_one;                  // runtime 1: adds become IMAD (fma pipe)

__device__ __forceinline__ uint32_t rotl32(uint32_t x, int r){ return __funnelshift_l(x, x, r); }

// plain threefry for setup
__device__ __forceinline__ uint2 tf2x32(uint32_t k0, uint32_t k1, uint32_t x0, uint32_t x1){
  uint32_t k2 = k0 ^ k1 ^ 0x1BD11BDAu;
  x0 += k0; x1 += k1;
#define TFR(r) { x0 += x1; x1 = rotl32(x1, (r)); x1 ^= x0; }
  TFR(13) TFR(15) TFR(26) TFR(6)
  x0 += k1; x1 += k2 + 1u;
  TFR(17) TFR(29) TFR(16) TFR(24)
  x0 += k2; x1 += k0 + 2u;
  TFR(13) TFR(15) TFR(26) TFR(6)
  x0 += k0; x1 += k1 + 3u;
  TFR(17) TFR(29) TFR(16) TFR(24)
  x0 += k1; x1 += k2 + 4u;
  TFR(13) TFR(15) TFR(26) TFR(6)
  x0 += k2; x1 += k0 + 5u;
#undef TFR
  return make_uint2(x0, x1);
}

// hot-loop threefry: expanded keys from smem; adds written x*one+y so ptxas
// emits IMAD (fma pipe). Pure C, no asm.
__device__ __forceinline__ uint32_t tf_bits(const uint4* ks, uint32_t p, uint32_t one){
  uint4 A = ks[0], B = ks[1], C = ks[2];
  uint32_t x0 = A.x;                       // 0 + k0
  uint32_t x1 = p*one + A.y;               // p + k1
#define TFR(r) { x0 = x0*one + x1; x1 = rotl32(x1, (r)) ^ x0; }
  TFR(13) TFR(15) TFR(26) TFR(6)
  x0 = x0*one + A.z; x1 = x1*one + A.w;    // +k1, +k2+1
  TFR(17) TFR(29) TFR(16) TFR(24)
  x0 = x0*one + B.x; x1 = x1*one + B.y;    // +k2, +k0+2
  TFR(13) TFR(15) TFR(26) TFR(6)
  x0 = x0*one + B.z; x1 = x1*one + B.w;    // +k0, +k1+3
  TFR(17) TFR(29) TFR(16) TFR(24)
  x0 = x0*one + C.x; x1 = x1*one + C.y;    // +k1, +k2+4
  TFR(13) TFR(15) TFR(26) TFR(6)
  x0 = x0*one + C.z; x1 = x1*one + C.w;    // +k2, +k0+5
#undef TFR
  return x0 ^ x1;                          // partitionable-mode bits
}

__global__ void k_setup(){
  int i = threadIdx.x;
  if (i <= NUM_STEPS){
    uint2 k = tf2x32(0u, 42u, 0u, (uint32_t)i);       // fold_in(key(42), i)
    uint32_t k0 = k.x, k1 = k.y, k2 = k0 ^ k1 ^ 0x1BD11BDAu;
    g_keys[3*i+0] = make_uint4(k0, k1, k1, k2+1u);
    g_keys[3*i+1] = make_uint4(k2, k0+2u, k0, k1+3u);
    g_keys[3*i+2] = make_uint4(k1, k2+4u, k2, k0+5u);
  }
  if (i == 0){ g_len_min_bits = 0x7F800000u; g_len_max_bits = 0u; g_one = 1u; }
}

// (B,4,D,D,D) -> (B, D^3, float4)
__global__ void k_pack(const float* __restrict__ tpl){
  int v = blockIdx.x*256 + threadIdx.x;
  int b = v >> 21;
  int r = v & (Vv-1);
  const float* base = tpl + (size_t)b*4*Vv;
  g_tpl[v] = make_float4(base[r], base[Vv+r], base[2*Vv+r], base[3*Vv+r]);
}

// Launch-slot shim: keeps k_march in the ncu profiled slot. No work.
__global__ void k_dummy(){ }

__global__ __launch_bounds__(128) void k_march(
  const float* __restrict__ rot, const float* __restrict__ campos,
  const float* __restrict__ fo,  const float* __restrict__ pp,
  const float* __restrict__ bg,  float* __restrict__ out)
{
  __shared__ uint4 skeys[(NUM_STEPS+1)*3];
  int lt = threadIdx.y*16 + threadIdx.x;
  for (int i = lt; i < (NUM_STEPS+1)*3; i += 128) skeys[i] = g_keys[i];
  __syncthreads();

  const uint32_t one = g_one;

  int w = blockIdx.x*16 + threadIdx.x;
  int h = blockIdx.y*8  + threadIdx.y;
  int b = blockIdx.z;
  int p = b*HW + h*Ww + w;

  float rx = ((float)w - pp[2*b+0]) / fo[2*b+0];
  float ry = ((float)h - pp[2*b+1]) / fo[2*b+1];
  const float* R = rot + 9*b;
  float dx = R[0]*rx + R[3]*ry + R[6];
  float dy = R[1]*rx + R[4]*ry + R[7];
  float dz = R[2]*rx + R[5]*ry + R[8];
  float nrm = sqrtf(dx*dx + dy*dy + dz*dz);
  dx /= nrm; dy /= nrm; dz /= nrm;
  float cxp = campos[3*b+0], cyp = campos[3*b+1], czp = campos[3*b+2];

  float t1x = (-1.0f-cxp)/dx, t2x = (1.0f-cxp)/dx;
  float t1y = (-1.0f-cyp)/dy, t2y = (1.0f-cyp)/dy;
  float t1z = (-1.0f-czp)/dz, t2z = (1.0f-czp)/dz;
  float tmin = fmaxf(fminf(t1x,t2x), fmaxf(fminf(t1y,t2y), fminf(t1z,t2z)));
  float tmax = fminf(fmaxf(t1x,t2x), fminf(fmaxf(t1y,t2y), fmaxf(t1z,t2z)));
  float t = (tmin < tmax) ? tmin : 0.0f;
  t = fmaxf(t, 0.0f);

  { // t jitter: uniform under fold_in(key,0)
    uint32_t bits = tf_bits(skeys, (uint32_t)p, one);
    float u = __uint_as_float((bits >> 9) | 0x3f800000u) - 1.0f;
    t = t - 0.02f * u;
  }

  float px = cxp + dx*t, py = cyp + dy*t, pz = czp + dz*t;
  float r0_=0.f, r1_=0.f, r2_=0.f, al=0.f, len=0.f;
  const float4* tp = g_tpl + (size_t)b*Vv;
  const float LO = -0.99999994f;
  const float LOm2 = LO - 2.0f;             // -2.99999994f, representable

  for (int i = 0; i < NUM_STEPS; i++){
    uint32_t bits = tf_bits(skeys + 3*(i+1), (uint32_t)p, one);
    float mant = __uint_as_float((bits >> 9) | 0x3f800000u);   // [1,2)
    float uu = fmaxf(LO, fmaf(mant, 2.0f, LOm2));
    // y = 0.01*sqrt(2)*erfinv(uu) in [-0.076, 0.076]
    float y = 0.014142136f * erfinvf(uu);
    // stepv = 0.02*exp(y) via cubic Taylor (rel err <= 1.4e-6 on this range)
    float stepv = fmaf(y, fmaf(y, fmaf(y, 0.0033333333f, 0.01f), 0.02f), 0.02f);

    float m = fmaxf(fmaxf(fabsf(px), fabsf(py)), fabsf(pz));
    float contrib = 0.0f;
    if (m < 1.0f && al < 1.0f){
      // inside ⇒ g in [0,127]; reference clip() is a no-op here.
      float gx = fmaf(px, 63.5f, 63.5f);
      float gy = fmaf(py, 63.5f, 63.5f);
      float gz = fmaf(pz, 63.5f, 63.5f);
      float x0f = floorf(gx), y0f = floorf(gy), z0f = floorf(gz);
      int x0 = (int)x0f; int x1 = min(x0+1,127); float wx = gx - x0f;
      int y0 = (int)y0f; int y1 = min(y0+1,127); float wy = gy - y0f;
      int z0 = (int)z0f; int z1 = min(z0+1,127); float wz = gz - z0f;
      int zy00 = (z0*Dd + y0)*Dd, zy01 = (z0*Dd + y1)*Dd;
      int zy10 = (z1*Dd + y0)*Dd, zy11 = (z1*Dd + y1)*Dd;
      float4 v000 = tp[zy00 + x0], v001 = tp[zy00 + x1];
      float4 v010 = tp[zy01 + x0], v011 = tp[zy01 + x1];
      float4 v100 = tp[zy10 + x0], v101 = tp[zy10 + x1];
      float4 v110 = tp[zy11 + x0], v111 = tp[zy11 + x1];
      float iwx = 1.0f - wx, iwy = 1.0f - wy, iwz = 1.0f - wz;
      float s0,s1,s2,s3;
#define TRI(ch, dst) { \
      float c00 = v000.ch*iwx + v001.ch*wx; \
      float c01 = v010.ch*iwx + v011.ch*wx; \
      float c10 = v100.ch*iwx + v101.ch*wx; \
      float c11 = v110.ch*iwx + v111.ch*wx; \
      float c0 = c00*iwy + c01*wy; \
      float c1 = c10*iwy + c11*wy; \
      dst = c0*iwz + c1*wz; }
      TRI(x,s0) TRI(y,s1) TRI(z,s2) TRI(w,s3)
#undef TRI
      contrib = fminf(al + s3*stepv, 1.0f) - al;
      r0_ += s0*contrib; r1_ += s1*contrib; r2_ += s2*contrib;
      al += contrib;
    }
    len += (contrib == 0.0f) ? stepv : 0.0f;
    px += dx*stepv; py += dy*stepv; pz += dz*stepv;
  }

  int pix = h*Ww + w;
  size_t rgbBase = (size_t)b*3*HW + pix;
  float ia = 1.0f - al;
  out[rgbBase       ] = r0_ + ia*fmaxf(bg[(size_t)(3*b+0)*HW + pix], 0.0f);
  out[rgbBase +   HW] = r1_ + ia*fmaxf(bg[(size_t)(3*b+1)*HW + pix], 0.0f);
  out[rgbBase + 2*HW] = r2_ + ia*fmaxf(bg[(size_t)(3*b+2)*HW + pix], 0.0f);
  out[(size_t)Bb*3*HW + b*HW + pix] = al;
  out[(size_t)Bb*4*HW + b*HW + pix] = len;   // raw; normalized by k_norm

  unsigned lb = __float_as_uint(len);
  unsigned mx = __reduce_max_sync(0xffffffffu, lb);
  unsigned mn = __reduce_min_sync(0xffffffffu, lb);
  if ((lt & 31) == 0){ atomicMax(&g_len_max_bits, mx); atomicMin(&g_len_min_bits, mn); }
}

__global__ void k_norm(float* __restrict__ out){
  int i = blockIdx.x*256 + threadIdx.x;
  float denom = __uint_as_float(g_len_max_bits) + __uint_as_float(g_len_min_bits);
  float a = out[(size_t)Bb*3*HW + i];
  float l = out[(size_t)Bb*4*HW + i];
  out[(size_t)Bb*4*HW + i] = (a * l) / denom;
}

extern "C" void kernel_launch(void* const* d_in, const int* in_sizes, int n_in,
                              void* d_out, int out_size) {
  const float* rot    = (const float*)d_in[0];
  const float* campos = (const float*)d_in[1];
  const float* fo     = (const float*)d_in[2];
  const float* pp     = (const float*)d_in[3];
  const float* tpl    = (const float*)d_in[5];
  const float* bg     = (const float*)d_in[6];
  float* out = (float*)d_out;

  k_setup<<<1, 256>>>();
  k_pack<<<(Bb*Vv)/256, 256>>>(tpl);
  k_dummy<<<1, 1>>>();                      // keeps k_march in ncu's profiled slot
  dim3 blk(16,8,1), grd(Ww/16, Hh/8, Bb);
  k_march<<<grd, blk>>>(rot, campos, fo, pp, bg, out);
  k_norm<<<(Bb*HW)/256, 256>>>(out);
}